// round 15
// baseline (speedup 1.0000x reference)
#include <cuda_runtime.h>
#include <cuda_bf16.h>
#include <cuda_fp16.h>
#include <cstdint>

#define BATCH   2
#define SEQ     2048
#define CMODEL  4096
#define NHEAD   32
#define DHEAD   128
#define NKV     8
#define GQA     4
#define MROWS   (BATCH * SEQ)
#define NQKV    (CMODEL + 2 * NKV * DHEAD)    // 6144 total projection cols

// ------------------------- device scratch (no allocs) ----------------------
__device__ __half g_qh[BATCH * NHEAD * SEQ * DHEAD];   // q fp16 hi
__device__ __half g_ql[BATCH * NHEAD * SEQ * DHEAD];   // q fp16 lo
__device__ __half g_kF[BATCH * NKV * SEQ * DHEAD];     // k fp16 (single)
__device__ __half g_vF[BATCH * NKV * SEQ * DHEAD];

__device__ __half g_xh [MROWS * CMODEL];               // fp16 hi of x
__device__ __half g_xl [MROWS * CMODEL];               // fp16 lo of x
__device__ __half g_wF [NQKV * CMODEL];                // wq|wk|wv transposed fp16
__device__ __half g_wotH[CMODEL * CMODEL];             // wo transposed fp16
__device__ __half g_aoF [MROWS * CMODEL];              // attention out fp16

// ------------------------- PTX helpers --------------------------------------
__device__ __forceinline__ uint32_t s2u(const void* p) {
    uint32_t a;
    asm("{ .reg .u64 t; cvta.to.shared.u64 t, %1; cvt.u32.u64 %0, t; }" : "=r"(a) : "l"(p));
    return a;
}
__device__ __forceinline__ void cpa16(uint32_t dst, const void* src) {
    asm volatile("cp.async.ca.shared.global [%0], [%1], 16;" :: "r"(dst), "l"(src));
}
__device__ __forceinline__ void cpa_commit() {
    asm volatile("cp.async.commit_group;" ::: "memory");
}
__device__ __forceinline__ void cpa_wait1() {
    asm volatile("cp.async.wait_group 1;" ::: "memory");
}
__device__ __forceinline__ void ldsm4(uint32_t& r0, uint32_t& r1, uint32_t& r2, uint32_t& r3,
                                      uint32_t addr) {
    asm volatile("ldmatrix.sync.aligned.m8n8.x4.shared.b16 {%0,%1,%2,%3}, [%4];"
                 : "=r"(r0), "=r"(r1), "=r"(r2), "=r"(r3) : "r"(addr));
}
__device__ __forceinline__ void ldsm4t(uint32_t& r0, uint32_t& r1, uint32_t& r2, uint32_t& r3,
                                       uint32_t addr) {
    asm volatile("ldmatrix.sync.aligned.m8n8.x4.trans.shared.b16 {%0,%1,%2,%3}, [%4];"
                 : "=r"(r0), "=r"(r1), "=r"(r2), "=r"(r3) : "r"(addr));
}
__device__ __forceinline__ void ldsm2(uint32_t& r0, uint32_t& r1, uint32_t addr) {
    asm volatile("ldmatrix.sync.aligned.m8n8.x2.shared.b16 {%0,%1}, [%2];"
                 : "=r"(r0), "=r"(r1) : "r"(addr));
}
__device__ __forceinline__ void mma16816h(float* c, uint32_t a0, uint32_t a1, uint32_t a2,
                                          uint32_t a3, uint32_t b0, uint32_t b1) {
    asm volatile("mma.sync.aligned.m16n8k16.row.col.f32.f16.f16.f32 "
                 "{%0,%1,%2,%3}, {%4,%5,%6,%7}, {%8,%9}, {%0,%1,%2,%3};"
                 : "+f"(c[0]), "+f"(c[1]), "+f"(c[2]), "+f"(c[3])
                 : "r"(a0), "r"(a1), "r"(a2), "r"(a3), "r"(b0), "r"(b1));
}
__device__ __forceinline__ uint32_t packh2(float a, float b) {
    const __half2 h = __floats2half2_rn(a, b);
    return *(const uint32_t*)&h;
}
__device__ __forceinline__ void split_pair_h(float a, float b,
                                             __half2& hi, __half2& lo) {
    const __half ha = __float2half(a), hb = __float2half(b);
    hi = __halves2half2(ha, hb);
    lo = __halves2half2(__float2half(a - __half2float(ha)),
                        __float2half(b - __half2float(hb)));
}

// ------------------------- conversion kernels -------------------------------
__global__ __launch_bounds__(256)
void fsplit_kernel(const float* __restrict__ s, __half* __restrict__ dh,
                   __half* __restrict__ dl, int n4) {
    int i = blockIdx.x * 256 + threadIdx.x;
    if (i >= n4) return;
    float4 v = ((const float4*)s)[i];
    __half2 h0, l0, h1, l1;
    split_pair_h(v.x, v.y, h0, l0);
    split_pair_h(v.z, v.w, h1, l1);
    ((__half2*)dh)[i * 2]     = h0;
    ((__half2*)dh)[i * 2 + 1] = h1;
    ((__half2*)dl)[i * 2]     = l0;
    ((__half2*)dl)[i * 2 + 1] = l1;
}

// transpose [K=4096][N] fp32 -> [row_off + N][4096] fp16
__global__ __launch_bounds__(256)
void thalf_kernel(const float* __restrict__ src, int N, __half* __restrict__ dst,
                  int row_off) {
    __shared__ float t[32][33];
    const int k0 = blockIdx.y * 32, n0 = blockIdx.x * 32;
    const int tx = threadIdx.x, ty = threadIdx.y;
    #pragma unroll
    for (int i = 0; i < 32; i += 8)
        t[ty + i][tx] = src[(size_t)(k0 + ty + i) * N + n0 + tx];
    __syncthreads();
    #pragma unroll
    for (int i = 0; i < 32; i += 8)
        dst[(size_t)(row_off + n0 + ty + i) * CMODEL + k0 + tx] = __float2half(t[tx][ty + i]);
}

// ------------------------- merged QKV projection GEMM -----------------------
// q/k regions: 2-pass (xh·w + xl·w) + RoPE ; v region: 1-pass (xh·w).
#define BKH 64
#define LDA 72
#define TILE_SM (128 * LDA)                 // 16-bit elems per tile
#define QK_STAGE_SM (3 * TILE_SM)           // xhi, xlo, w
#define QK_SMEM (2 * QK_STAGE_SM * 2)       // 110592 B

__device__ __forceinline__ void load_tile_async_h(const __half* __restrict__ g,
                                                  int row0, int col0, uint32_t sdst, int tid) {
    const char* gp = (const char*)(g + (size_t)row0 * CMODEL + col0);
    #pragma unroll
    for (int i = 0; i < 4; i++) {
        const int idx = i * 256 + tid;
        const int r = idx >> 3, cb = (idx & 7) << 4;
        cpa16(sdst + (uint32_t)(r * (LDA * 2) + cb), gp + (size_t)r * (CMODEL * 2) + cb);
    }
}

__global__ __launch_bounds__(256)
void gemm_qkv(const __half* __restrict__ Ah, const __half* __restrict__ Al,
              const __half* __restrict__ W,
              const float* __restrict__ cosp, const float* __restrict__ sinp)
{
    extern __shared__ __half sm[];
    const uint32_t base = s2u(sm);

    const int tid  = threadIdx.x;
    const int wid  = tid >> 5, lane = tid & 31;
    const int wm   = wid >> 2;
    const int wn   = wid & 3;
    const int n0   = blockIdx.x * 128, m0 = blockIdx.y * 128;
    const bool isV = (n0 >= CMODEL + 1024);

    float acc[4][4][4];
    #pragma unroll
    for (int i = 0; i < 4; i++)
        #pragma unroll
        for (int j = 0; j < 4; j++)
            #pragma unroll
            for (int c = 0; c < 4; c++) acc[i][j][c] = 0.f;

    const uint32_t aOff = (uint32_t)((wm * 64 + (lane & 15)) * (LDA * 2) + (lane >> 4) * 16);
    const uint32_t bOff = (uint32_t)((wn * 32 + (lane & 7)) * (LDA * 2) + ((lane & 15) >> 3) * 16);

    {
        load_tile_async_h(Ah, m0, 0, base + 0 * TILE_SM * 2, tid);
        if (!isV) load_tile_async_h(Al, m0, 0, base + 1 * TILE_SM * 2, tid);
        load_tile_async_h(W,  n0, 0, base + 2 * TILE_SM * 2, tid);
        cpa_commit();
    }

    const int NIT = CMODEL / BKH;
    for (int it = 0; it < NIT; it++) {
        if (it + 1 < NIT) {
            const uint32_t sn = base + ((it + 1) & 1) * QK_STAGE_SM * 2;
            const int kc = (it + 1) * BKH;
            load_tile_async_h(Ah, m0, kc, sn + 0 * TILE_SM * 2, tid);
            if (!isV) load_tile_async_h(Al, m0, kc, sn + 1 * TILE_SM * 2, tid);
            load_tile_async_h(W,  n0, kc, sn + 2 * TILE_SM * 2, tid);
        }
        cpa_commit();
        cpa_wait1();
        __syncthreads();

        const uint32_t sc = base + (it & 1) * QK_STAGE_SM * 2;
        const uint32_t uAh = sc, uAl = sc + TILE_SM * 2, uB = sc + 2 * TILE_SM * 2;

        #pragma unroll
        for (int ks = 0; ks < 4; ks++) {
            const uint32_t kb = ks * 32;
            uint32_t ah[4][4], al[4][4], b[4][2];
            #pragma unroll
            for (int mf = 0; mf < 4; mf++)
                ldsm4(ah[mf][0], ah[mf][1], ah[mf][2], ah[mf][3],
                      uAh + aOff + mf * (16 * LDA * 2) + kb);
            if (!isV) {
                #pragma unroll
                for (int mf = 0; mf < 4; mf++)
                    ldsm4(al[mf][0], al[mf][1], al[mf][2], al[mf][3],
                          uAl + aOff + mf * (16 * LDA * 2) + kb);
            }
            #pragma unroll
            for (int nf = 0; nf < 4; nf++)
                ldsm2(b[nf][0], b[nf][1], uB + bOff + nf * (8 * LDA * 2) + kb);
            #pragma unroll
            for (int mf = 0; mf < 4; mf++)
                #pragma unroll
                for (int nf = 0; nf < 4; nf++) {
                    mma16816h(acc[mf][nf], ah[mf][0], ah[mf][1], ah[mf][2], ah[mf][3],
                              b[nf][0], b[nf][1]);
                    if (!isV)
                        mma16816h(acc[mf][nf], al[mf][0], al[mf][1], al[mf][2], al[mf][3],
                                  b[nf][0], b[nf][1]);
                }
        }
        __syncthreads();
    }

    const int group = lane >> 2, tig = lane & 3;
    const int isQ = (n0 < CMODEL);
    const int head = isQ ? (n0 >> 7) : (isV ? ((n0 - CMODEL - 1024) >> 7)
                                            : ((n0 - CMODEL) >> 7));
    const int nh   = isQ ? NHEAD : NKV;

    #pragma unroll
    for (int mf = 0; mf < 4; mf++) {
        #pragma unroll
        for (int nf = 0; nf < 4; nf++) {
            const int d = wn * 32 + nf * 8 + tig * 2;
            #pragma unroll
            for (int half = 0; half < 2; half++) {
                const int row = m0 + wm * 64 + mf * 16 + group + half * 8;
                const int bb = row >> 11, tt = row & (SEQ - 1);
                float e = acc[mf][nf][half * 2], o = acc[mf][nf][half * 2 + 1];
                const size_t off = ((size_t)(bb * nh + head) * SEQ + tt) * DHEAD + d;
                if (isV) {
                    *(__half2*)(g_vF + off) = __floats2half2_rn(e, o);
                } else {
                    const float ct = cosp[tt * DHEAD + d];
                    const float st = sinp[tt * DHEAD + d];
                    const float ne = e * ct - o * st;
                    o = e * st + o * ct;
                    e = ne;
                    if (isQ) {
                        __half2 hi, lo;
                        split_pair_h(e, o, hi, lo);
                        *(__half2*)(g_qh + off) = hi;
                        *(__half2*)(g_ql + off) = lo;
                    } else {
                        *(__half2*)(g_kF + off) = __floats2half2_rn(e, o);
                    }
                }
            }
        }
    }
}

// ------------------------- 1-pass fp16 HMMA GEMM (output projection) --------
#define OP_STAGE_SM (2 * TILE_SM)
#define OP_SMEM (2 * OP_STAGE_SM * 2)          // 73728 B

__global__ __launch_bounds__(256, 2)
void gemm_op(const __half* __restrict__ A, const __half* __restrict__ B,
             float* __restrict__ outp)
{
    extern __shared__ __half smh[];
    const uint32_t base = s2u(smh);

    const int tid  = threadIdx.x;
    const int wid  = tid >> 5, lane = tid & 31;
    const int wm   = wid >> 2;
    const int wn   = wid & 3;
    const int n0   = blockIdx.x * 128, m0 = blockIdx.y * 128;

    float acc[4][4][4];
    #pragma unroll
    for (int i = 0; i < 4; i++)
        #pragma unroll
        for (int j = 0; j < 4; j++)
            #pragma unroll
            for (int c = 0; c < 4; c++) acc[i][j][c] = 0.f;

    const uint32_t aOff = (uint32_t)((wm * 64 + (lane & 15)) * (LDA * 2) + (lane >> 4) * 16);
    const uint32_t bOff = (uint32_t)((wn * 32 + (lane & 7)) * (LDA * 2) + ((lane & 15) >> 3) * 16);

    {
        load_tile_async_h(A, m0, 0, base, tid);
        load_tile_async_h(B, n0, 0, base + TILE_SM * 2, tid);
        cpa_commit();
    }

    const int NIT = CMODEL / BKH;
    for (int it = 0; it < NIT; it++) {
        if (it + 1 < NIT) {
            const uint32_t sn = base + ((it + 1) & 1) * OP_STAGE_SM * 2;
            const int kc = (it + 1) * BKH;
            load_tile_async_h(A, m0, kc, sn, tid);
            load_tile_async_h(B, n0, kc, sn + TILE_SM * 2, tid);
        }
        cpa_commit();
        cpa_wait1();
        __syncthreads();

        const uint32_t sc = base + (it & 1) * OP_STAGE_SM * 2;
        const uint32_t uA = sc, uB = sc + TILE_SM * 2;

        #pragma unroll
        for (int ks = 0; ks < 4; ks++) {
            const uint32_t kb = ks * 32;
            uint32_t a[4][4], b[4][2];
            #pragma unroll
            for (int mf = 0; mf < 4; mf++)
                ldsm4(a[mf][0], a[mf][1], a[mf][2], a[mf][3],
                      uA + aOff + mf * (16 * LDA * 2) + kb);
            #pragma unroll
            for (int nf = 0; nf < 4; nf++)
                ldsm2(b[nf][0], b[nf][1], uB + bOff + nf * (8 * LDA * 2) + kb);
            #pragma unroll
            for (int mf = 0; mf < 4; mf++)
                #pragma unroll
                for (int nf = 0; nf < 4; nf++)
                    mma16816h(acc[mf][nf], a[mf][0], a[mf][1], a[mf][2], a[mf][3],
                              b[nf][0], b[nf][1]);
        }
        __syncthreads();
    }

    const int group = lane >> 2, tig = lane & 3;
    #pragma unroll
    for (int mf = 0; mf < 4; mf++) {
        #pragma unroll
        for (int nf = 0; nf < 4; nf++) {
            const int d = wn * 32 + nf * 8 + tig * 2;
            #pragma unroll
            for (int half = 0; half < 2; half++) {
                const int row = m0 + wm * 64 + mf * 16 + group + half * 8;
                float* dst = outp + (size_t)row * CMODEL + n0 + d;
                *(float2*)dst = make_float2(acc[mf][nf][half * 2], acc[mf][nf][half * 2 + 1]);
            }
        }
    }
}

// ===========================================================================
// HMMA flash attention: 2-pass fp16 QK, 1-pass fp16 PV.
// Q fragments cached in registers; P stays in registers; K/V double-buffered.
// ===========================================================================
#define FBQ 128
#define FBK 64
#define SQK 136
#define KVT (FBK * SQK)                         // halfs per K or V tile
#define FLASH_SMEM ((2 * FBQ * SQK + 4 * KVT) * 2)   // 139264 B

__global__ __launch_bounds__(256, 1)
void flash_mma_kernel(const int* __restrict__ is_causal_p)
{
    extern __shared__ char fsmc[];
    __half* Qh = (__half*)fsmc;
    __half* Ql = Qh + FBQ * SQK;
    __half* KV = Ql + FBQ * SQK;   // [stage][K tile | V tile]

    const int tid  = threadIdx.x;
    const int wid  = tid >> 5, lane = tid & 31;
    const int g    = lane >> 2, tig = lane & 3;
    const int qi   = (gridDim.x - 1) - blockIdx.x;
    const int h    = blockIdx.y, b = blockIdx.z;
    const int kh   = h >> 2;
    const float scale = 0.08838834764831845f;

    const __half* qgh = g_qh + ((size_t)(b * NHEAD + h) * SEQ + qi * FBQ) * DHEAD;
    const __half* qgl = g_ql + ((size_t)(b * NHEAD + h) * SEQ + qi * FBQ) * DHEAD;
    const __half* kgf = g_kF + (size_t)(b * NKV + kh) * SEQ * DHEAD;
    const __half* vgf = g_vF + (size_t)(b * NKV + kh) * SEQ * DHEAD;

    const uint32_t uQh = s2u(Qh), uQl = s2u(Ql), uKV = s2u(KV);

    // Q load (group 0)
    #pragma unroll
    for (int i = 0; i < 8; i++) {
        const int idx = i * 256 + tid;
        const int r = idx >> 4, c = (idx & 15) << 3;
        cpa16(uQh + (uint32_t)(r * SQK + c) * 2, qgh + (size_t)r * DHEAD + c);
        cpa16(uQl + (uint32_t)(r * SQK + c) * 2, qgl + (size_t)r * DHEAD + c);
    }
    cpa_commit();

    const int causal = is_causal_p[0];
    const int nkt = causal ? (2 * qi + 2) : (SEQ / FBK);

    // K/V tile 0 into stage 0 (group 1)
    #pragma unroll
    for (int i = 0; i < 4; i++) {
        const int idx = i * 256 + tid;
        const int r = idx >> 4, c = (idx & 15) << 3;
        const uint32_t so = (uint32_t)(r * SQK + c) * 2;
        cpa16(uKV + so,              kgf + (size_t)r * DHEAD + c);
        cpa16(uKV + KVT * 2 + so,    vgf + (size_t)r * DHEAD + c);
    }
    cpa_commit();

    float oc[16][4];
    #pragma unroll
    for (int i = 0; i < 16; i++)
        #pragma unroll
        for (int c = 0; c < 4; c++) oc[i][c] = 0.f;
    float mrow[2] = {-1e30f, -1e30f}, lrow[2] = {0.f, 0.f};

    uint32_t qhr[8][4], qlr[8][4];      // Q fragments cached across K-loop

    const uint32_t aQ = (uint32_t)((wid * 16 + (lane & 15)) * (SQK * 2) + ((lane >> 4) << 4));
    const int brow = (lane & 7) + ((lane >> 4) << 3);
    const uint32_t bcol = ((lane >> 3) & 1) << 4;
    const int vkrow = (lane & 7) + (((lane >> 3) & 1) << 3);
    const int vdcol = (lane >> 4) << 3;
    const int warpRow0 = qi * FBQ + wid * 16;

    for (int kt = 0; kt < nkt; kt++) {
        if (kt + 1 < nkt) {
            const uint32_t sn = uKV + ((kt + 1) & 1) * (2 * KVT * 2);
            #pragma unroll
            for (int i = 0; i < 4; i++) {
                const int idx = i * 256 + tid;
                const int r = idx >> 4, c = (idx & 15) << 3;
                const size_t go = ((size_t)(kt + 1) * FBK + r) * DHEAD + c;
                const uint32_t so = (uint32_t)(r * SQK + c) * 2;
                cpa16(sn + so,           kgf + go);
                cpa16(sn + KVT * 2 + so, vgf + go);
            }
        }
        cpa_commit();
        cpa_wait1();
        __syncthreads();

        if (kt == 0) {
            #pragma unroll
            for (int ks = 0; ks < 8; ks++) {
                ldsm4(qhr[ks][0], qhr[ks][1], qhr[ks][2], qhr[ks][3], uQh + aQ + ks * 32);
                ldsm4(qlr[ks][0], qlr[ks][1], qlr[ks][2], qlr[ks][3], uQl + aQ + ks * 32);
            }
        }

        const uint32_t uKf = uKV + (kt & 1) * (2 * KVT * 2);
        const uint32_t uVf = uKf + KVT * 2;
        const bool dead = causal && (kt * FBK > warpRow0 + 15);

        if (!dead) {
            // ---- S = Q K^T (2-pass: qh*k + ql*k) --------------------------
            float sc[8][4];
            #pragma unroll
            for (int i = 0; i < 8; i++)
                #pragma unroll
                for (int c = 0; c < 4; c++) sc[i][c] = 0.f;

            #pragma unroll
            for (int ks = 0; ks < 8; ks++) {
                const uint32_t kb = ks * 32;
                #pragma unroll
                for (int j = 0; j < 4; j++) {
                    const uint32_t ro = (uint32_t)((j * 16 + brow) * (SQK * 2)) + bcol + kb;
                    uint32_t bf0, bf1, bf2, bf3;
                    ldsm4(bf0, bf1, bf2, bf3, uKf + ro);
                    mma16816h(sc[2 * j],     qhr[ks][0], qhr[ks][1], qhr[ks][2], qhr[ks][3], bf0, bf1);
                    mma16816h(sc[2 * j],     qlr[ks][0], qlr[ks][1], qlr[ks][2], qlr[ks][3], bf0, bf1);
                    mma16816h(sc[2 * j + 1], qhr[ks][0], qhr[ks][1], qhr[ks][2], qhr[ks][3], bf2, bf3);
                    mma16816h(sc[2 * j + 1], qlr[ks][0], qlr[ks][1], qlr[ks][2], qlr[ks][3], bf2, bf3);
                }
            }

            const int rowA = warpRow0 + g;
            const bool mb = causal && (kt >= 2 * qi);
            #pragma unroll
            for (int nf = 0; nf < 8; nf++)
                #pragma unroll
                for (int c = 0; c < 4; c++) {
                    float v = sc[nf][c] * scale;
                    if (mb) {
                        const int col = kt * FBK + nf * 8 + 2 * tig + (c & 1);
                        const int row = rowA + ((c >> 1) << 3);
                        if (col > row) v = -1e30f;
                    }
                    sc[nf][c] = v;
                }

            // ---- online softmax -------------------------------------------
            #pragma unroll
            for (int half = 0; half < 2; half++) {
                float mx = -1e30f;
                #pragma unroll
                for (int nf = 0; nf < 8; nf++)
                    mx = fmaxf(mx, fmaxf(sc[nf][half * 2], sc[nf][half * 2 + 1]));
                mx = fmaxf(mx, __shfl_xor_sync(0xffffffffu, mx, 1));
                mx = fmaxf(mx, __shfl_xor_sync(0xffffffffu, mx, 2));
                const float mnew  = fmaxf(mrow[half], mx);
                const float alpha = __expf(mrow[half] - mnew);
                float ps = 0.f;
                #pragma unroll
                for (int nf = 0; nf < 8; nf++) {
                    const float p0 = __expf(sc[nf][half * 2]     - mnew);
                    const float p1 = __expf(sc[nf][half * 2 + 1] - mnew);
                    sc[nf][half * 2] = p0; sc[nf][half * 2 + 1] = p1;
                    ps += p0 + p1;
                }
                ps += __shfl_xor_sync(0xffffffffu, ps, 1);
                ps += __shfl_xor_sync(0xffffffffu, ps, 2);
                lrow[half] = lrow[half] * alpha + ps;
                mrow[half] = mnew;
                #pragma unroll
                for (int i = 0; i < 16; i++) {
                    oc[i][half * 2]     *= alpha;
                    oc[i][half * 2 + 1] *= alpha;
                }
            }

            // ---- O += P V : P fed directly from registers -----------------
            #pragma unroll
            for (int ks = 0; ks < 4; ks++) {
                const uint32_t p0 = packh2(sc[2 * ks][0],     sc[2 * ks][1]);
                const uint32_t p1 = packh2(sc[2 * ks][2],     sc[2 * ks][3]);
                const uint32_t p2 = packh2(sc[2 * ks + 1][0], sc[2 * ks + 1][1]);
                const uint32_t p3 = packh2(sc[2 * ks + 1][2], sc[2 * ks + 1][3]);
                #pragma unroll
                for (int j = 0; j < 8; j++) {
                    const uint32_t vo = (uint32_t)((ks * 16 + vkrow) * (SQK * 2)
                                                   + (j * 16 + vdcol) * 2);
                    uint32_t vf0, vf1, vf2, vf3;
                    ldsm4t(vf0, vf1, vf2, vf3, uVf + vo);
                    mma16816h(oc[2 * j],     p0, p1, p2, p3, vf0, vf1);
                    mma16816h(oc[2 * j + 1], p0, p1, p2, p3, vf2, vf3);
                }
            }
        }
        __syncthreads();
    }

    // ---- epilogue: normalize and emit fp16 O -------------------------------
    const float inv0 = 1.0f / lrow[0], inv1 = 1.0f / lrow[1];
    const int row0 = b * SEQ + qi * FBQ + wid * 16 + g;
    const int cb   = h * DHEAD + 2 * tig;
    #pragma unroll
    for (int nfo = 0; nfo < 16; nfo++) {
        const int col = cb + nfo * 8;
        *(__half2*)(g_aoF + (size_t)row0 * CMODEL + col) =
            __floats2half2_rn(oc[nfo][0] * inv0, oc[nfo][1] * inv0);
        *(__half2*)(g_aoF + (size_t)(row0 + 8) * CMODEL + col) =
            __floats2half2_rn(oc[nfo][2] * inv1, oc[nfo][3] * inv1);
    }
}

// ===========================================================================
// Launch
// ===========================================================================
extern "C" void kernel_launch(void* const* d_in, const int* in_sizes, int n_in,
                              void* d_out, int out_size)
{
    const float* x    = (const float*)d_in[0];
    const float* wq   = (const float*)d_in[1];
    const float* wk   = (const float*)d_in[2];
    const float* wv   = (const float*)d_in[3];
    const float* wo   = (const float*)d_in[4];
    const float* cosp = (const float*)d_in[5];
    const float* sinp = (const float*)d_in[6];
    const int*   isc  = (const int*)d_in[7];

    __half *xh, *xl, *wF, *wotH, *aoF;
    cudaGetSymbolAddress((void**)&xh,   g_xh);
    cudaGetSymbolAddress((void**)&xl,   g_xl);
    cudaGetSymbolAddress((void**)&wF,   g_wF);
    cudaGetSymbolAddress((void**)&wotH, g_wotH);
    cudaGetSymbolAddress((void**)&aoF,  g_aoF);

    // 1) split x into fp16 hi/lo
    fsplit_kernel<<<(MROWS * CMODEL / 4 + 255) / 256, 256>>>(x, xh, xl, MROWS * CMODEL / 4);

    // 2) transpose weights to fp16: wq|wk|wv concat, wo
    dim3 tb(32, 8);
    thalf_kernel<<<dim3(CMODEL / 32, CMODEL / 32), tb>>>(wq, CMODEL, wF, 0);
    thalf_kernel<<<dim3(1024 / 32,   CMODEL / 32), tb>>>(wk, 1024,   wF, CMODEL);
    thalf_kernel<<<dim3(1024 / 32,   CMODEL / 32), tb>>>(wv, 1024,   wF, CMODEL + 1024);
    thalf_kernel<<<dim3(CMODEL / 32, CMODEL / 32), tb>>>(wo, CMODEL, wotH, 0);

    // 3) merged QKV projection (q/k 2-pass + RoPE, v 1-pass)
    cudaFuncSetAttribute(gemm_qkv, cudaFuncAttributeMaxDynamicSharedMemorySize, QK_SMEM);
    gemm_qkv<<<dim3(NQKV / 128, MROWS / 128), 256, QK_SMEM>>>(
        xh, xl, wF, cosp, sinp);

    // 4) HMMA flash attention (2-pass QK, register Q/P, K/V pipelined)
    cudaFuncSetAttribute(flash_mma_kernel, cudaFuncAttributeMaxDynamicSharedMemorySize,
                         FLASH_SMEM);
    dim3 g2(SEQ / FBQ, NHEAD, BATCH);
    flash_mma_kernel<<<g2, 256, FLASH_SMEM>>>(isc);

    // 5) output projection (1-pass fp16 HMMA)
    cudaFuncSetAttribute(gemm_op, cudaFuncAttributeMaxDynamicSharedMemorySize, OP_SMEM);
    gemm_op<<<dim3(CMODEL / 128, MROWS / 128), 256, OP_SMEM>>>(
        aoF, wotH, (float*)d_out);
}

// round 16
// speedup vs baseline: 1.5615x; 1.5615x over previous
#include <cuda_runtime.h>
#include <cuda_bf16.h>
#include <cuda_fp16.h>
#include <cstdint>

#define BATCH   2
#define SEQ     2048
#define CMODEL  4096
#define NHEAD   32
#define DHEAD   128
#define NKV     8
#define GQA     4
#define MROWS   (BATCH * SEQ)
#define NQK     (CMODEL + NKV * DHEAD)        // 5120 (q+k projection cols)

// ------------------------- device scratch (no allocs) ----------------------
__device__ __half g_qh[BATCH * NHEAD * SEQ * DHEAD];   // q fp16 hi
__device__ __half g_ql[BATCH * NHEAD * SEQ * DHEAD];   // q fp16 lo
__device__ __half g_kF[BATCH * NKV * SEQ * DHEAD];     // k fp16 (single)
__device__ __half g_vF[BATCH * NKV * SEQ * DHEAD];

__device__ __half g_xh [MROWS * CMODEL];               // fp16 hi of x (also V input)
__device__ __half g_xl [MROWS * CMODEL];               // fp16 lo of x
__device__ __half g_wqkF[NQK * CMODEL];                // wq|wk transposed fp16
__device__ __half g_wvtF[(NKV * DHEAD) * CMODEL];      // wv transposed fp16
__device__ __half g_wotH[CMODEL * CMODEL];             // wo transposed fp16
__device__ __half g_aoF [MROWS * CMODEL];              // attention out fp16

// ------------------------- PTX helpers --------------------------------------
__device__ __forceinline__ uint32_t s2u(const void* p) {
    uint32_t a;
    asm("{ .reg .u64 t; cvta.to.shared.u64 t, %1; cvt.u32.u64 %0, t; }" : "=r"(a) : "l"(p));
    return a;
}
__device__ __forceinline__ void cpa16(uint32_t dst, const void* src) {
    asm volatile("cp.async.ca.shared.global [%0], [%1], 16;" :: "r"(dst), "l"(src));
}
__device__ __forceinline__ void cpa_commit() {
    asm volatile("cp.async.commit_group;" ::: "memory");
}
__device__ __forceinline__ void cpa_wait1() {
    asm volatile("cp.async.wait_group 1;" ::: "memory");
}
__device__ __forceinline__ void ldsm4(uint32_t& r0, uint32_t& r1, uint32_t& r2, uint32_t& r3,
                                      uint32_t addr) {
    asm volatile("ldmatrix.sync.aligned.m8n8.x4.shared.b16 {%0,%1,%2,%3}, [%4];"
                 : "=r"(r0), "=r"(r1), "=r"(r2), "=r"(r3) : "r"(addr));
}
__device__ __forceinline__ void ldsm4t(uint32_t& r0, uint32_t& r1, uint32_t& r2, uint32_t& r3,
                                       uint32_t addr) {
    asm volatile("ldmatrix.sync.aligned.m8n8.x4.trans.shared.b16 {%0,%1,%2,%3}, [%4];"
                 : "=r"(r0), "=r"(r1), "=r"(r2), "=r"(r3) : "r"(addr));
}
__device__ __forceinline__ void ldsm2(uint32_t& r0, uint32_t& r1, uint32_t addr) {
    asm volatile("ldmatrix.sync.aligned.m8n8.x2.shared.b16 {%0,%1}, [%2];"
                 : "=r"(r0), "=r"(r1) : "r"(addr));
}
__device__ __forceinline__ void mma16816h(float* c, uint32_t a0, uint32_t a1, uint32_t a2,
                                          uint32_t a3, uint32_t b0, uint32_t b1) {
    asm volatile("mma.sync.aligned.m16n8k16.row.col.f32.f16.f16.f32 "
                 "{%0,%1,%2,%3}, {%4,%5,%6,%7}, {%8,%9}, {%0,%1,%2,%3};"
                 : "+f"(c[0]), "+f"(c[1]), "+f"(c[2]), "+f"(c[3])
                 : "r"(a0), "r"(a1), "r"(a2), "r"(a3), "r"(b0), "r"(b1));
}
__device__ __forceinline__ uint32_t packh2(float a, float b) {
    const __half2 h = __floats2half2_rn(a, b);
    return *(const uint32_t*)&h;
}
__device__ __forceinline__ void split_pair_h(float a, float b,
                                             __half2& hi, __half2& lo) {
    const __half ha = __float2half(a), hb = __float2half(b);
    hi = __halves2half2(ha, hb);
    lo = __halves2half2(__float2half(a - __half2float(ha)),
                        __float2half(b - __half2float(hb)));
}

// ------------------------- conversion kernels -------------------------------
// fp32 -> fp16 hi/lo
__global__ __launch_bounds__(256)
void fsplit_kernel(const float* __restrict__ s, __half* __restrict__ dh,
                   __half* __restrict__ dl, int n4) {
    int i = blockIdx.x * 256 + threadIdx.x;
    if (i >= n4) return;
    float4 v = ((const float4*)s)[i];
    __half2 h0, l0, h1, l1;
    split_pair_h(v.x, v.y, h0, l0);
    split_pair_h(v.z, v.w, h1, l1);
    ((__half2*)dh)[i * 2]     = h0;
    ((__half2*)dh)[i * 2 + 1] = h1;
    ((__half2*)dl)[i * 2]     = l0;
    ((__half2*)dl)[i * 2 + 1] = l1;
}

// transpose [K=4096][N] fp32 -> [row_off + N][4096] fp16
__global__ __launch_bounds__(256)
void thalf_kernel(const float* __restrict__ src, int N, __half* __restrict__ dst,
                  int row_off) {
    __shared__ float t[32][33];
    const int k0 = blockIdx.y * 32, n0 = blockIdx.x * 32;
    const int tx = threadIdx.x, ty = threadIdx.y;
    #pragma unroll
    for (int i = 0; i < 32; i += 8)
        t[ty + i][tx] = src[(size_t)(k0 + ty + i) * N + n0 + tx];
    __syncthreads();
    #pragma unroll
    for (int i = 0; i < 32; i += 8)
        dst[(size_t)(row_off + n0 + ty + i) * CMODEL + k0 + tx] = __float2half(t[tx][ty + i]);
}

// ------------------------- 2-pass fp16 HMMA GEMM (Q+K projection) -----------
#define BKH 64
#define LDA 72
#define TILE_SM (128 * LDA)                 // 16-bit elems per tile
#define QK_STAGE_SM (3 * TILE_SM)           // xhi, xlo, w
#define QK_SMEM (2 * QK_STAGE_SM * 2)       // 110592 B

__device__ __forceinline__ void load_tile_async_h(const __half* __restrict__ g,
                                                  int row0, int col0, uint32_t sdst, int tid) {
    const char* gp = (const char*)(g + (size_t)row0 * CMODEL + col0);
    #pragma unroll
    for (int i = 0; i < 4; i++) {
        const int idx = i * 256 + tid;
        const int r = idx >> 3, cb = (idx & 7) << 4;
        cpa16(sdst + (uint32_t)(r * (LDA * 2) + cb), gp + (size_t)r * (CMODEL * 2) + cb);
    }
}

__global__ __launch_bounds__(256)
void gemm_qk(const __half* __restrict__ Ah, const __half* __restrict__ Al,
             const __half* __restrict__ B,
             const float* __restrict__ cosp, const float* __restrict__ sinp)
{
    extern __shared__ __half sm[];
    const uint32_t base = s2u(sm);

    const int tid  = threadIdx.x;
    const int wid  = tid >> 5, lane = tid & 31;
    const int wm   = wid >> 2;
    const int wn   = wid & 3;
    const int n0   = blockIdx.x * 128, m0 = blockIdx.y * 128;

    float acc[4][4][4];
    #pragma unroll
    for (int i = 0; i < 4; i++)
        #pragma unroll
        for (int j = 0; j < 4; j++)
            #pragma unroll
            for (int c = 0; c < 4; c++) acc[i][j][c] = 0.f;

    const uint32_t aOff = (uint32_t)((wm * 64 + (lane & 15)) * (LDA * 2) + (lane >> 4) * 16);
    const uint32_t bOff = (uint32_t)((wn * 32 + (lane & 7)) * (LDA * 2) + ((lane & 15) >> 3) * 16);

    {
        load_tile_async_h(Ah, m0, 0, base + 0 * TILE_SM * 2, tid);
        load_tile_async_h(Al, m0, 0, base + 1 * TILE_SM * 2, tid);
        load_tile_async_h(B,  n0, 0, base + 2 * TILE_SM * 2, tid);
        cpa_commit();
    }

    const int NIT = CMODEL / BKH;
    for (int it = 0; it < NIT; it++) {
        if (it + 1 < NIT) {
            const uint32_t sn = base + ((it + 1) & 1) * QK_STAGE_SM * 2;
            const int kc = (it + 1) * BKH;
            load_tile_async_h(Ah, m0, kc, sn + 0 * TILE_SM * 2, tid);
            load_tile_async_h(Al, m0, kc, sn + 1 * TILE_SM * 2, tid);
            load_tile_async_h(B,  n0, kc, sn + 2 * TILE_SM * 2, tid);
        }
        cpa_commit();
        cpa_wait1();
        __syncthreads();

        const uint32_t sc = base + (it & 1) * QK_STAGE_SM * 2;
        const uint32_t uAh = sc, uAl = sc + TILE_SM * 2, uB = sc + 2 * TILE_SM * 2;

        #pragma unroll
        for (int ks = 0; ks < 4; ks++) {
            const uint32_t kb = ks * 32;
            uint32_t ah[4][4], al[4][4], b[4][2];
            #pragma unroll
            for (int mf = 0; mf < 4; mf++) {
                ldsm4(ah[mf][0], ah[mf][1], ah[mf][2], ah[mf][3],
                      uAh + aOff + mf * (16 * LDA * 2) + kb);
                ldsm4(al[mf][0], al[mf][1], al[mf][2], al[mf][3],
                      uAl + aOff + mf * (16 * LDA * 2) + kb);
            }
            #pragma unroll
            for (int nf = 0; nf < 4; nf++)
                ldsm2(b[nf][0], b[nf][1], uB + bOff + nf * (8 * LDA * 2) + kb);
            #pragma unroll
            for (int mf = 0; mf < 4; mf++)
                #pragma unroll
                for (int nf = 0; nf < 4; nf++) {
                    mma16816h(acc[mf][nf], ah[mf][0], ah[mf][1], ah[mf][2], ah[mf][3],
                              b[nf][0], b[nf][1]);
                    mma16816h(acc[mf][nf], al[mf][0], al[mf][1], al[mf][2], al[mf][3],
                              b[nf][0], b[nf][1]);
                }
        }
        __syncthreads();
    }

    const int group = lane >> 2, tig = lane & 3;
    const int isQ = (n0 < CMODEL);
    const int head = isQ ? (n0 >> 7) : ((n0 - CMODEL) >> 7);
    const int nh   = isQ ? NHEAD : NKV;

    #pragma unroll
    for (int mf = 0; mf < 4; mf++) {
        #pragma unroll
        for (int nf = 0; nf < 4; nf++) {
            const int d = wn * 32 + nf * 8 + tig * 2;
            #pragma unroll
            for (int half = 0; half < 2; half++) {
                const int row = m0 + wm * 64 + mf * 16 + group + half * 8;
                const int bb = row >> 11, tt = row & (SEQ - 1);
                float e = acc[mf][nf][half * 2], o = acc[mf][nf][half * 2 + 1];
                const float ct = cosp[tt * DHEAD + d];
                const float st = sinp[tt * DHEAD + d];
                const float ne = e * ct - o * st;
                o = e * st + o * ct;
                e = ne;
                const size_t off = ((size_t)(bb * nh + head) * SEQ + tt) * DHEAD + d;
                if (isQ) {
                    __half2 hi, lo;
                    split_pair_h(e, o, hi, lo);
                    *(__half2*)(g_qh + off) = hi;
                    *(__half2*)(g_ql + off) = lo;
                } else {
                    *(__half2*)(g_kF + off) = __floats2half2_rn(e, o);
                }
            }
        }
    }
}

// ------------------------- 1-pass fp16 HMMA GEMM ----------------------------
// MODE 0: V projection -> g_vF scatter ; MODE 1: out proj -> float out
#define OP_STAGE_SM (2 * TILE_SM)
#define OP_SMEM (2 * OP_STAGE_SM * 2)          // 73728 B

template<int MODE>
__global__ __launch_bounds__(256, 2)
void gemm_h(const __half* __restrict__ A, const __half* __restrict__ B,
            float* __restrict__ outp)
{
    extern __shared__ __half smh[];
    const uint32_t base = s2u(smh);

    const int tid  = threadIdx.x;
    const int wid  = tid >> 5, lane = tid & 31;
    const int wm   = wid >> 2;
    const int wn   = wid & 3;
    const int n0   = blockIdx.x * 128, m0 = blockIdx.y * 128;

    float acc[4][4][4];
    #pragma unroll
    for (int i = 0; i < 4; i++)
        #pragma unroll
        for (int j = 0; j < 4; j++)
            #pragma unroll
            for (int c = 0; c < 4; c++) acc[i][j][c] = 0.f;

    const uint32_t aOff = (uint32_t)((wm * 64 + (lane & 15)) * (LDA * 2) + (lane >> 4) * 16);
    const uint32_t bOff = (uint32_t)((wn * 32 + (lane & 7)) * (LDA * 2) + ((lane & 15) >> 3) * 16);

    {
        load_tile_async_h(A, m0, 0, base, tid);
        load_tile_async_h(B, n0, 0, base + TILE_SM * 2, tid);
        cpa_commit();
    }

    const int NIT = CMODEL / BKH;
    for (int it = 0; it < NIT; it++) {
        if (it + 1 < NIT) {
            const uint32_t sn = base + ((it + 1) & 1) * OP_STAGE_SM * 2;
            const int kc = (it + 1) * BKH;
            load_tile_async_h(A, m0, kc, sn, tid);
            load_tile_async_h(B, n0, kc, sn + TILE_SM * 2, tid);
        }
        cpa_commit();
        cpa_wait1();
        __syncthreads();

        const uint32_t sc = base + (it & 1) * OP_STAGE_SM * 2;
        const uint32_t uA = sc, uB = sc + TILE_SM * 2;

        #pragma unroll
        for (int ks = 0; ks < 4; ks++) {
            const uint32_t kb = ks * 32;
            uint32_t a[4][4], b[4][2];
            #pragma unroll
            for (int mf = 0; mf < 4; mf++)
                ldsm4(a[mf][0], a[mf][1], a[mf][2], a[mf][3],
                      uA + aOff + mf * (16 * LDA * 2) + kb);
            #pragma unroll
            for (int nf = 0; nf < 4; nf++)
                ldsm2(b[nf][0], b[nf][1], uB + bOff + nf * (8 * LDA * 2) + kb);
            #pragma unroll
            for (int mf = 0; mf < 4; mf++)
                #pragma unroll
                for (int nf = 0; nf < 4; nf++)
                    mma16816h(acc[mf][nf], a[mf][0], a[mf][1], a[mf][2], a[mf][3],
                              b[nf][0], b[nf][1]);
        }
        __syncthreads();
    }

    const int group = lane >> 2, tig = lane & 3;
    if (MODE == 0) {
        const int head = n0 >> 7;
        #pragma unroll
        for (int mf = 0; mf < 4; mf++) {
            #pragma unroll
            for (int nf = 0; nf < 4; nf++) {
                const int d = wn * 32 + nf * 8 + tig * 2;
                #pragma unroll
                for (int half = 0; half < 2; half++) {
                    const int row = m0 + wm * 64 + mf * 16 + group + half * 8;
                    const int bb = row >> 11, tt = row & (SEQ - 1);
                    const size_t off = ((size_t)(bb * NKV + head) * SEQ + tt) * DHEAD + d;
                    *(__half2*)(g_vF + off) =
                        __floats2half2_rn(acc[mf][nf][half * 2], acc[mf][nf][half * 2 + 1]);
                }
            }
        }
    } else {
        #pragma unroll
        for (int mf = 0; mf < 4; mf++) {
            #pragma unroll
            for (int nf = 0; nf < 4; nf++) {
                const int d = wn * 32 + nf * 8 + tig * 2;
                #pragma unroll
                for (int half = 0; half < 2; half++) {
                    const int row = m0 + wm * 64 + mf * 16 + group + half * 8;
                    float* dst = outp + (size_t)row * CMODEL + n0 + d;
                    *(float2*)dst = make_float2(acc[mf][nf][half * 2], acc[mf][nf][half * 2 + 1]);
                }
            }
        }
    }
}

// ===========================================================================
// HMMA flash attention: 2-pass fp16 QK, 1-pass fp16 PV.
// P stays in registers (C-fragment of S == A-fragment for PV).
// K/V double-buffered via cp.async; fully-masked diagonal warp-tiles skipped.
// ===========================================================================
#define FBQ 128
#define FBK 64
#define SQK 136
#define KVT (FBK * SQK)                         // halfs per K or V tile
#define FLASH_SMEM ((2 * FBQ * SQK + 4 * KVT) * 2)   // 139264 B

__global__ __launch_bounds__(256, 1)
void flash_mma_kernel(const int* __restrict__ is_causal_p)
{
    extern __shared__ char fsmc[];
    __half* Qh = (__half*)fsmc;
    __half* Ql = Qh + FBQ * SQK;
    __half* KV = Ql + FBQ * SQK;   // [stage][K tile | V tile]

    const int tid  = threadIdx.x;
    const int wid  = tid >> 5, lane = tid & 31;
    const int g    = lane >> 2, tig = lane & 3;
    const int qi   = (gridDim.x - 1) - blockIdx.x;
    const int h    = blockIdx.y, b = blockIdx.z;
    const int kh   = h >> 2;
    const float scale = 0.08838834764831845f;

    const __half* qgh = g_qh + ((size_t)(b * NHEAD + h) * SEQ + qi * FBQ) * DHEAD;
    const __half* qgl = g_ql + ((size_t)(b * NHEAD + h) * SEQ + qi * FBQ) * DHEAD;
    const __half* kgf = g_kF + (size_t)(b * NKV + kh) * SEQ * DHEAD;
    const __half* vgf = g_vF + (size_t)(b * NKV + kh) * SEQ * DHEAD;

    const uint32_t uQh = s2u(Qh), uQl = s2u(Ql), uKV = s2u(KV);

    // Q load (group 0)
    #pragma unroll
    for (int i = 0; i < 8; i++) {
        const int idx = i * 256 + tid;
        const int r = idx >> 4, c = (idx & 15) << 3;
        cpa16(uQh + (uint32_t)(r * SQK + c) * 2, qgh + (size_t)r * DHEAD + c);
        cpa16(uQl + (uint32_t)(r * SQK + c) * 2, qgl + (size_t)r * DHEAD + c);
    }
    cpa_commit();

    const int causal = is_causal_p[0];
    const int nkt = causal ? (2 * qi + 2) : (SEQ / FBK);

    // K/V tile 0 into stage 0 (group 1)
    #pragma unroll
    for (int i = 0; i < 4; i++) {
        const int idx = i * 256 + tid;
        const int r = idx >> 4, c = (idx & 15) << 3;
        const uint32_t so = (uint32_t)(r * SQK + c) * 2;
        cpa16(uKV + so,              kgf + (size_t)r * DHEAD + c);
        cpa16(uKV + KVT * 2 + so,    vgf + (size_t)r * DHEAD + c);
    }
    cpa_commit();

    float oc[16][4];
    #pragma unroll
    for (int i = 0; i < 16; i++)
        #pragma unroll
        for (int c = 0; c < 4; c++) oc[i][c] = 0.f;
    float mrow[2] = {-1e30f, -1e30f}, lrow[2] = {0.f, 0.f};

    const uint32_t aQ = (uint32_t)((wid * 16 + (lane & 15)) * (SQK * 2) + ((lane >> 4) << 4));
    const int brow = (lane & 7) + ((lane >> 4) << 3);
    const uint32_t bcol = ((lane >> 3) & 1) << 4;
    const int vkrow = (lane & 7) + (((lane >> 3) & 1) << 3);
    const int vdcol = (lane >> 4) << 3;
    const int warpRow0 = qi * FBQ + wid * 16;     // first row this warp owns

    for (int kt = 0; kt < nkt; kt++) {
        // prefetch next K/V tile into the other stage
        if (kt + 1 < nkt) {
            const uint32_t sn = uKV + ((kt + 1) & 1) * (2 * KVT * 2);
            #pragma unroll
            for (int i = 0; i < 4; i++) {
                const int idx = i * 256 + tid;
                const int r = idx >> 4, c = (idx & 15) << 3;
                const size_t go = ((size_t)(kt + 1) * FBK + r) * DHEAD + c;
                const uint32_t so = (uint32_t)(r * SQK + c) * 2;
                cpa16(sn + so,           kgf + go);
                cpa16(sn + KVT * 2 + so, vgf + go);
            }
        }
        cpa_commit();
        cpa_wait1();          // current stage (and Q on iter 0) complete
        __syncthreads();

        const uint32_t uKf = uKV + (kt & 1) * (2 * KVT * 2);
        const uint32_t uVf = uKf + KVT * 2;

        // Fully-masked diagonal warp-tile? (smallest col > largest row)
        const bool dead = causal && (kt * FBK > warpRow0 + 15);

        if (!dead) {
            // ---- S = Q K^T (2-pass: qh*k + ql*k) --------------------------
            float sc[8][4];
            #pragma unroll
            for (int i = 0; i < 8; i++)
                #pragma unroll
                for (int c = 0; c < 4; c++) sc[i][c] = 0.f;

            #pragma unroll
            for (int ks = 0; ks < 8; ks++) {
                const uint32_t kb = ks * 32;
                uint32_t ah0, ah1, ah2, ah3, al0, al1, al2, al3;
                ldsm4(ah0, ah1, ah2, ah3, uQh + aQ + kb);
                ldsm4(al0, al1, al2, al3, uQl + aQ + kb);
                #pragma unroll
                for (int j = 0; j < 4; j++) {
                    const uint32_t ro = (uint32_t)((j * 16 + brow) * (SQK * 2)) + bcol + kb;
                    uint32_t bf0, bf1, bf2, bf3;
                    ldsm4(bf0, bf1, bf2, bf3, uKf + ro);
                    mma16816h(sc[2 * j],     ah0, ah1, ah2, ah3, bf0, bf1);
                    mma16816h(sc[2 * j],     al0, al1, al2, al3, bf0, bf1);
                    mma16816h(sc[2 * j + 1], ah0, ah1, ah2, ah3, bf2, bf3);
                    mma16816h(sc[2 * j + 1], al0, al1, al2, al3, bf2, bf3);
                }
            }

            const int rowA = warpRow0 + g;
            const bool mb = causal && (kt >= 2 * qi);
            #pragma unroll
            for (int nf = 0; nf < 8; nf++)
                #pragma unroll
                for (int c = 0; c < 4; c++) {
                    float v = sc[nf][c] * scale;
                    if (mb) {
                        const int col = kt * FBK + nf * 8 + 2 * tig + (c & 1);
                        const int row = rowA + ((c >> 1) << 3);
                        if (col > row) v = -1e30f;
                    }
                    sc[nf][c] = v;
                }

            // ---- online softmax -------------------------------------------
            #pragma unroll
            for (int half = 0; half < 2; half++) {
                float mx = -1e30f;
                #pragma unroll
                for (int nf = 0; nf < 8; nf++)
                    mx = fmaxf(mx, fmaxf(sc[nf][half * 2], sc[nf][half * 2 + 1]));
                mx = fmaxf(mx, __shfl_xor_sync(0xffffffffu, mx, 1));
                mx = fmaxf(mx, __shfl_xor_sync(0xffffffffu, mx, 2));
                const float mnew  = fmaxf(mrow[half], mx);
                const float alpha = __expf(mrow[half] - mnew);
                float ps = 0.f;
                #pragma unroll
                for (int nf = 0; nf < 8; nf++) {
                    const float p0 = __expf(sc[nf][half * 2]     - mnew);
                    const float p1 = __expf(sc[nf][half * 2 + 1] - mnew);
                    sc[nf][half * 2] = p0; sc[nf][half * 2 + 1] = p1;
                    ps += p0 + p1;
                }
                ps += __shfl_xor_sync(0xffffffffu, ps, 1);
                ps += __shfl_xor_sync(0xffffffffu, ps, 2);
                lrow[half] = lrow[half] * alpha + ps;
                mrow[half] = mnew;
                #pragma unroll
                for (int i = 0; i < 16; i++) {
                    oc[i][half * 2]     *= alpha;
                    oc[i][half * 2 + 1] *= alpha;
                }
            }

            // ---- O += P V : P fed directly from registers -----------------
            #pragma unroll
            for (int ks = 0; ks < 4; ks++) {
                const uint32_t p0 = packh2(sc[2 * ks][0],     sc[2 * ks][1]);
                const uint32_t p1 = packh2(sc[2 * ks][2],     sc[2 * ks][3]);
                const uint32_t p2 = packh2(sc[2 * ks + 1][0], sc[2 * ks + 1][1]);
                const uint32_t p3 = packh2(sc[2 * ks + 1][2], sc[2 * ks + 1][3]);
                #pragma unroll
                for (int j = 0; j < 8; j++) {
                    const uint32_t vo = (uint32_t)((ks * 16 + vkrow) * (SQK * 2)
                                                   + (j * 16 + vdcol) * 2);
                    uint32_t vf0, vf1, vf2, vf3;
                    ldsm4t(vf0, vf1, vf2, vf3, uVf + vo);
                    mma16816h(oc[2 * j],     p0, p1, p2, p3, vf0, vf1);
                    mma16816h(oc[2 * j + 1], p0, p1, p2, p3, vf2, vf3);
                }
            }
        }
        __syncthreads();    // all warps done reading this stage before refill
    }

    // ---- epilogue: normalize and emit fp16 O -------------------------------
    const float inv0 = 1.0f / lrow[0], inv1 = 1.0f / lrow[1];
    const int row0 = b * SEQ + qi * FBQ + wid * 16 + g;
    const int cb   = h * DHEAD + 2 * tig;
    #pragma unroll
    for (int nfo = 0; nfo < 16; nfo++) {
        const int col = cb + nfo * 8;
        *(__half2*)(g_aoF + (size_t)row0 * CMODEL + col) =
            __floats2half2_rn(oc[nfo][0] * inv0, oc[nfo][1] * inv0);
        *(__half2*)(g_aoF + (size_t)(row0 + 8) * CMODEL + col) =
            __floats2half2_rn(oc[nfo][2] * inv1, oc[nfo][3] * inv1);
    }
}

// ===========================================================================
// Launch
// ===========================================================================
extern "C" void kernel_launch(void* const* d_in, const int* in_sizes, int n_in,
                              void* d_out, int out_size)
{
    const float* x    = (const float*)d_in[0];
    const float* wq   = (const float*)d_in[1];
    const float* wk   = (const float*)d_in[2];
    const float* wv   = (const float*)d_in[3];
    const float* wo   = (const float*)d_in[4];
    const float* cosp = (const float*)d_in[5];
    const float* sinp = (const float*)d_in[6];
    const int*   isc  = (const int*)d_in[7];

    __half *xh, *xl, *wqkF, *wvtF, *wotH, *aoF;
    cudaGetSymbolAddress((void**)&xh,   g_xh);
    cudaGetSymbolAddress((void**)&xl,   g_xl);
    cudaGetSymbolAddress((void**)&wqkF, g_wqkF);
    cudaGetSymbolAddress((void**)&wvtF, g_wvtF);
    cudaGetSymbolAddress((void**)&wotH, g_wotH);
    cudaGetSymbolAddress((void**)&aoF,  g_aoF);

    // 1) split x into fp16 hi/lo (hi also feeds V projection)
    fsplit_kernel<<<(MROWS * CMODEL / 4 + 255) / 256, 256>>>(x, xh, xl, MROWS * CMODEL / 4);

    // 2) transpose weights to fp16: wq|wk concat, wv, wo
    dim3 tb(32, 8);
    thalf_kernel<<<dim3(CMODEL / 32, CMODEL / 32), tb>>>(wq, CMODEL, wqkF, 0);
    thalf_kernel<<<dim3(1024 / 32,   CMODEL / 32), tb>>>(wk, 1024,   wqkF, CMODEL);
    thalf_kernel<<<dim3(1024 / 32,   CMODEL / 32), tb>>>(wv, 1024,   wvtF, 0);
    thalf_kernel<<<dim3(CMODEL / 32, CMODEL / 32), tb>>>(wo, CMODEL, wotH, 0);

    // 3) Q+K projection (2-pass fp16 HMMA) + RoPE -> q hi/lo, k single fp16
    cudaFuncSetAttribute(gemm_qk, cudaFuncAttributeMaxDynamicSharedMemorySize, QK_SMEM);
    gemm_qk<<<dim3(NQK / 128, MROWS / 128), 256, QK_SMEM>>>(
        xh, xl, wqkF, cosp, sinp);

    // 4) V projection (1-pass fp16 HMMA)
    cudaFuncSetAttribute(gemm_h<0>, cudaFuncAttributeMaxDynamicSharedMemorySize, OP_SMEM);
    gemm_h<0><<<dim3(1024 / 128, MROWS / 128), 256, OP_SMEM>>>(xh, wvtF, nullptr);

    // 5) HMMA flash attention (2-pass QK, register-P 1-pass PV, K/V pipelined)
    cudaFuncSetAttribute(flash_mma_kernel, cudaFuncAttributeMaxDynamicSharedMemorySize,
                         FLASH_SMEM);
    dim3 g2(SEQ / FBQ, NHEAD, BATCH);
    flash_mma_kernel<<<g2, 256, FLASH_SMEM>>>(isc);

    // 6) output projection (1-pass fp16 HMMA)
    cudaFuncSetAttribute(gemm_h<1>, cudaFuncAttributeMaxDynamicSharedMemorySize, OP_SMEM);
    gemm_h<1><<<dim3(CMODEL / 128, MROWS / 128), 256, OP_SMEM>>>(
        aoF, wotH, (float*)d_out);
}